// round 10
// baseline (speedup 1.0000x reference)
#include <cuda_runtime.h>

#define NTHREADS 256
#define TB 4
#define EDIM 1024
#define NQ 8

typedef unsigned long long u64;

__device__ __forceinline__ u64 pack2(float lo, float hi) {
    u64 r; asm("mov.b64 %0, {%1, %2};" : "=l"(r) : "f"(lo), "f"(hi)); return r;
}
__device__ __forceinline__ u64 packdup(float v) {
    u64 r; asm("mov.b64 %0, {%1, %1};" : "=l"(r) : "f"(v)); return r;
}
__device__ __forceinline__ void unpack2(u64 p, float& lo, float& hi) {
    asm("mov.b64 {%0, %1}, %2;" : "=f"(lo), "=f"(hi) : "l"(p));
}
__device__ __forceinline__ u64 mul2(u64 a, u64 b) {
    u64 r; asm("mul.rn.f32x2 %0, %1, %2;" : "=l"(r) : "l"(a), "l"(b)); return r;
}
__device__ __forceinline__ u64 fma2(u64 a, u64 b, u64 c) {
    u64 r; asm("fma.rn.f32x2 %0, %1, %2, %3;" : "=l"(r) : "l"(a), "l"(b), "l"(c)); return r;
}
__device__ __forceinline__ u64 add2(u64 a, u64 b) {
    u64 r; asm("add.rn.f32x2 %0, %1, %2;" : "=l"(r) : "l"(a), "l"(b)); return r;
}

// psum buffer (unpaired, R5 layout): psumA [TB][256 float4] = qubits 0-3,
// psumB [TB][256 float4] = qubits 4-7. 32 KB per buffer, double-buffered.
#define PSB_OFF   16384u
#define PS_STRIDE 32768u
#define ZD_OFF    65536u                 // two zdup buffers, 512 B each
#define CTH_OFF   (ZD_OFF + 1024u)
#define BI_OFF    (CTH_OFF + 32u)
#define SMEM_BYTES (BI_OFF + 32u)        // 66,624 B -> 2 CTAs/SM

__global__ __launch_bounds__(NTHREADS, 2)
void qff_fused(const float* __restrict__ x,
               const float* __restrict__ W_in,
               const float* __restrict__ b_in,
               const float* __restrict__ theta,
               const float* __restrict__ W_out,
               const float* __restrict__ b_out,
               float* __restrict__ out,
               int n_tokens)
{
    extern __shared__ char smc[];
    float* cth = reinterpret_cast<float*>(smc + CTH_OFF);
    float* bi  = reinterpret_cast<float*>(smc + BI_OFF);

    const int tid  = threadIdx.x;
    const int lane = tid & 31;
    const int wrp  = tid >> 5;

    if (tid < NQ) { cth[tid] = cosf(theta[tid]); bi[tid] = b_in[tid]; }

    // ---- W_in pairs: wi[pr][c] = (W_in[2pr][4t+c], W_in[2pr+1][4t+c]) ----
    u64 wi[4][4];
#pragma unroll
    for (int pr = 0; pr < 4; pr++) {
        float4 wa = reinterpret_cast<const float4*>(W_in + (2*pr  )*EDIM)[tid];
        float4 wb = reinterpret_cast<const float4*>(W_in + (2*pr+1)*EDIM)[tid];
        wi[pr][0] = pack2(wa.x, wb.x);
        wi[pr][1] = pack2(wa.y, wb.y);
        wi[pr][2] = pack2(wa.z, wb.z);
        wi[pr][3] = pack2(wa.w, wb.w);
    }
    // ---- W_out pairs + bias ----
    u64 wo01[8], wo23[8], bo01, bo23;
    {
        float4 rA[4], rB[4];
#pragma unroll
        for (int j = 0; j < 4; j++) {
            rA[j] = reinterpret_cast<const float4*>(W_out)[(4*tid+j)*2 + 0];
            rB[j] = reinterpret_cast<const float4*>(W_out)[(4*tid+j)*2 + 1];
        }
        wo01[0]=pack2(rA[0].x,rA[1].x); wo01[1]=pack2(rA[0].y,rA[1].y);
        wo01[2]=pack2(rA[0].z,rA[1].z); wo01[3]=pack2(rA[0].w,rA[1].w);
        wo01[4]=pack2(rB[0].x,rB[1].x); wo01[5]=pack2(rB[0].y,rB[1].y);
        wo01[6]=pack2(rB[0].z,rB[1].z); wo01[7]=pack2(rB[0].w,rB[1].w);
        wo23[0]=pack2(rA[2].x,rA[3].x); wo23[1]=pack2(rA[2].y,rA[3].y);
        wo23[2]=pack2(rA[2].z,rA[3].z); wo23[3]=pack2(rA[2].w,rA[3].w);
        wo23[4]=pack2(rB[2].x,rB[3].x); wo23[5]=pack2(rB[2].y,rB[3].y);
        wo23[6]=pack2(rB[2].z,rB[3].z); wo23[7]=pack2(rB[2].w,rB[3].w);
        float4 bo = reinterpret_cast<const float4*>(b_out)[tid];
        bo01 = pack2(bo.x, bo.y); bo23 = pack2(bo.z, bo.w);
    }

    // stage-2 lane constants (warps 0..3 only; warp w = token w)
    const int pr2 = lane >> 3;           // qubit pair 0..3
    const int c8  = lane & 7;            // chunk: elements i = c8 + 8j
    const unsigned s2_off = ((pr2 & 2) ? PSB_OFF : 0u)
                          + (unsigned)wrp * 4096u
                          + (unsigned)c8 * 16u
                          + ((pr2 & 1) ? 8u : 0u);

    const int nbatches = n_tokens / TB;          // 8192
    const int stride   = gridDim.x;
    const int blk      = blockIdx.x;
    const int M = (nbatches - blk + stride - 1) / stride;

    const float4* x4 = reinterpret_cast<const float4*>(x);
    float4* out4 = reinterpret_cast<float4*>(out);

    float4 xv[TB];
    #define LOADX(bb) { const float4* xr_ = x4 + (long)(bb)*TB*(EDIM/4) + tid; \
        _Pragma("unroll") for (int t_ = 0; t_ < TB; t_++) xv[t_] = xr_[t_*(EDIM/4)]; }

    LOADX(blk);

    for (int r = 0; r <= M + 1; r++) {
        const int par = r & 1;
        char* psumW = smc + (par ? PS_STRIDE : 0u);
        char* psumR = smc + (par ? 0u : PS_STRIDE);
        float* zdW  = reinterpret_cast<float*>(smc + ZD_OFF + (par ? 512u : 0u));
        float* zdR  = reinterpret_cast<float*>(smc + ZD_OFF + (par ? 0u : 512u));

        // ---- phase 1 on batch r (writes psum[par]); prefetch batch r+1 ----
        if (r < M) {
#pragma unroll
            for (int t = 0; t < TB; t++) {
                u64 xx = packdup(xv[t].x), xy = packdup(xv[t].y);
                u64 xz = packdup(xv[t].z), xw = packdup(xv[t].w);
                u64 p0 = mul2(xx, wi[0][0]); p0 = fma2(xy, wi[0][1], p0);
                p0 = fma2(xz, wi[0][2], p0); p0 = fma2(xw, wi[0][3], p0);
                u64 p1 = mul2(xx, wi[1][0]); p1 = fma2(xy, wi[1][1], p1);
                p1 = fma2(xz, wi[1][2], p1); p1 = fma2(xw, wi[1][3], p1);
                u64 p2 = mul2(xx, wi[2][0]); p2 = fma2(xy, wi[2][1], p2);
                p2 = fma2(xz, wi[2][2], p2); p2 = fma2(xw, wi[2][3], p2);
                u64 p3 = mul2(xx, wi[3][0]); p3 = fma2(xy, wi[3][1], p3);
                p3 = fma2(xz, wi[3][2], p3); p3 = fma2(xw, wi[3][3], p3);
                // STS.128 x2: psumA {q0..q3}, psumB {q4..q7}
                reinterpret_cast<ulonglong2*>(psumW + (unsigned)t*4096u)[tid]
                    = make_ulonglong2(p0, p1);
                reinterpret_cast<ulonglong2*>(psumW + PSB_OFF + (unsigned)t*4096u)[tid]
                    = make_ulonglong2(p2, p3);
            }
            if (r + 1 < M) { const int bnext = blk + (r + 1) * stride; LOADX(bnext); }
        }

        // ---- stage 2 on batch r-1 (warps 0..3; reads psum[par^1]) ----
        if (wrp < TB && r >= 1 && r - 1 < M) {
            const char* sb = psumR + s2_off;
            u64 a0 = *reinterpret_cast<const u64*>(sb + 128u*0);
            u64 a1 = *reinterpret_cast<const u64*>(sb + 128u*1);
            u64 a2 = *reinterpret_cast<const u64*>(sb + 128u*2);
            u64 a3 = *reinterpret_cast<const u64*>(sb + 128u*3);
#pragma unroll
            for (int j = 4; j < 32; j += 4) {
                a0 = add2(a0, *reinterpret_cast<const u64*>(sb + 128u*(j+0)));
                a1 = add2(a1, *reinterpret_cast<const u64*>(sb + 128u*(j+1)));
                a2 = add2(a2, *reinterpret_cast<const u64*>(sb + 128u*(j+2)));
                a3 = add2(a3, *reinterpret_cast<const u64*>(sb + 128u*(j+3)));
            }
            u64 acc = add2(add2(a0, a1), add2(a2, a3));
            acc = add2(acc, __shfl_down_sync(0xffffffffu, acc, 4, 8));
            acc = add2(acc, __shfl_down_sync(0xffffffffu, acc, 2, 8));
            acc = add2(acc, __shfl_down_sync(0xffffffffu, acc, 1, 8));
            float sa, sb2; unpack2(acc, sa, sb2);
            float ma = cth[2*pr2  ] * cosf(sa  + bi[2*pr2  ]);
            float mb = cth[2*pr2+1] * cosf(sb2 + bi[2*pr2+1]);
            float pp = ma * mb;
            float incl = pp, tt;
            tt = __shfl_up_sync(0xffffffffu, incl, 8);  if (lane >= 8)  incl *= tt;
            tt = __shfl_up_sync(0xffffffffu, incl, 16); if (lane >= 16) incl *= tt;
            float E = __shfl_up_sync(0xffffffffu, incl, 8);
            if (pr2 == 0) E = 1.0f;
            float za = E * ma, zb = E * pp;
            if (c8 == 0)
                reinterpret_cast<float4*>(zdW + wrp*16)[pr2] = make_float4(za, za, zb, zb);
        }

        // ---- phase 3 on batch r-2 (reads zdup[par^1]) ----
        if (r >= 2) {
            const int bb = blk + (r - 2) * stride;
            float4* orow = out4 + (long)bb * TB * (EDIM/4) + tid;
#pragma unroll
            for (int t = 0; t < TB; t++) {
                const ulonglong2* zr = reinterpret_cast<const ulonglong2*>(zdR + t*16);
                ulonglong2 z01 = zr[0], z23 = zr[1], z45 = zr[2], z67 = zr[3];
                u64 acc01 = bo01, acc23 = bo23;
                acc01 = fma2(z01.x, wo01[0], acc01);  acc23 = fma2(z01.x, wo23[0], acc23);
                acc01 = fma2(z01.y, wo01[1], acc01);  acc23 = fma2(z01.y, wo23[1], acc23);
                acc01 = fma2(z23.x, wo01[2], acc01);  acc23 = fma2(z23.x, wo23[2], acc23);
                acc01 = fma2(z23.y, wo01[3], acc01);  acc23 = fma2(z23.y, wo23[3], acc23);
                acc01 = fma2(z45.x, wo01[4], acc01);  acc23 = fma2(z45.x, wo23[4], acc23);
                acc01 = fma2(z45.y, wo01[5], acc01);  acc23 = fma2(z45.y, wo23[5], acc23);
                acc01 = fma2(z67.x, wo01[6], acc01);  acc23 = fma2(z67.x, wo23[6], acc23);
                acc01 = fma2(z67.y, wo01[7], acc01);  acc23 = fma2(z67.y, wo23[7], acc23);
                float a0, a1, a2, a3;
                unpack2(acc01, a0, a1); unpack2(acc23, a2, a3);
                orow[t*(EDIM/4)] = make_float4(fmaxf(a0,0.f), fmaxf(a1,0.f),
                                               fmaxf(a2,0.f), fmaxf(a3,0.f));
            }
        }

        __syncthreads();   // single barrier separates all cross-region hazards
    }
    #undef LOADX
}

extern "C" void kernel_launch(void* const* d_in, const int* in_sizes, int n_in,
                              void* d_out, int out_size) {
    const float* x     = (const float*)d_in[0];
    const float* W_in  = (const float*)d_in[1];
    const float* b_in  = (const float*)d_in[2];
    const float* theta = (const float*)d_in[3];
    const float* W_out = (const float*)d_in[4];
    const float* b_out = (const float*)d_in[5];
    float* out = (float*)d_out;

    const int n_tokens = in_sizes[0] / EDIM;   // 32768

    cudaFuncSetAttribute(qff_fused, cudaFuncAttributeMaxDynamicSharedMemorySize,
                         (int)SMEM_BYTES);
    qff_fused<<<296, NTHREADS, SMEM_BYTES>>>(x, W_in, b_in, theta, W_out, b_out,
                                             out, n_tokens);
}